// round 10
// baseline (speedup 1.0000x reference)
#include <cuda_runtime.h>
#include <cstdint>

// ---------------------------------------------------------------------------
// Problem constants
// ---------------------------------------------------------------------------
static constexpr int KD = 4096;
static constexpr int ND = 4096;
static constexpr int MD = 4096;
static constexpr int NGROUPS = 32;     // K groups of 128

// GEMM tiling: CTA 128x128, K-group (=128) per mainloop iteration
static constexpr int BM = 128;
static constexpr int BN = 128;
static constexpr int GK = 128;          // K per iteration = one scale group
static constexpr int NITER = KD / GK;   // 32
static constexpr int STAGES = 3;
static constexpr int THREADS = 256;

// SMEM stage layout: int8 tiles, 144B row stride (128 data + 16 pad)
static constexpr int ROWB = 144;
static constexpr int TILE_B = 128 * ROWB;          // 18432
static constexpr int OFF_AH = 0;
static constexpr int OFF_AL = TILE_B;
static constexpr int OFF_B  = 2 * TILE_B;
static constexpr int STAGE_BYTES = 3 * TILE_B;     // 55296
static constexpr int SC_BYTES = NGROUPS * BN * 4;  // 16384
static constexpr int SMEM_TOTAL = SC_BYTES + STAGES * STAGE_BYTES;  // 182272

// ---------------------------------------------------------------------------
// Scratch: A digits [M,K] int8 (hi/lo), B = (q-zp) transposed [N,K] int8,
// per-token scale sx[M].
// ---------------------------------------------------------------------------
__device__ int8_t g_Ahi[(size_t)MD * KD];
__device__ int8_t g_Alo[(size_t)MD * KD];
__device__ int8_t g_Bd [(size_t)ND * KD];
__device__ float  g_sx [MD];

// ---------------------------------------------------------------------------
// PTX helpers (sm_80-era, valid on compute_103 virtual target)
// ---------------------------------------------------------------------------
__device__ __forceinline__ uint32_t smem_u32(const void* p) {
    uint32_t a;
    asm("{ .reg .u64 t; cvta.to.shared.u64 t, %1; cvt.u32.u64 %0, t; }" : "=r"(a) : "l"(p));
    return a;
}
__device__ __forceinline__ void cp_async16(uint32_t dst, const void* src) {
    asm volatile("cp.async.cg.shared.global [%0], [%1], 16;" :: "r"(dst), "l"(src));
}
__device__ __forceinline__ void cp_commit() {
    asm volatile("cp.async.commit_group;" ::: "memory");
}
__device__ __forceinline__ void ldsm4(uint32_t* r, uint32_t addr) {
    asm volatile("ldmatrix.sync.aligned.m8n8.x4.shared.b16 {%0,%1,%2,%3}, [%4];"
                 : "=r"(r[0]), "=r"(r[1]), "=r"(r[2]), "=r"(r[3]) : "r"(addr));
}
// D(s32) += A(s8 16x32) * B(s8 32x8)
__device__ __forceinline__ void mma_s8(int* c, const uint32_t* a, const uint32_t* b) {
    asm volatile(
        "mma.sync.aligned.m16n8k32.row.col.s32.s8.s8.s32 "
        "{%0,%1,%2,%3}, {%4,%5,%6,%7}, {%8,%9}, {%0,%1,%2,%3};"
        : "+r"(c[0]), "+r"(c[1]), "+r"(c[2]), "+r"(c[3])
        : "r"(a[0]), "r"(a[1]), "r"(a[2]), "r"(a[3]), "r"(b[0]), "r"(b[1]));
}

__device__ __forceinline__ int pack4(int a, int b, int c, int d) {
    return (a & 255) | ((b & 255) << 8) | ((c & 255) << 16) | (d << 24);
}

// ---------------------------------------------------------------------------
// Prep 1: per-token two-digit int8 quantization of x.
// x[m,k] = sx[m] * (128*hi + lo) + eps,  |hi|<=127, |lo|<=64.
// One block per token row; 256 threads x 16 elements.
// ---------------------------------------------------------------------------
__global__ __launch_bounds__(256) void quant_x_kernel(const float* __restrict__ x) {
    const int m = blockIdx.x;
    const int t = threadIdx.x;
    const float4* xr = reinterpret_cast<const float4*>(x + (size_t)m * KD) + t * 4;
    float4 v[4];
    #pragma unroll
    for (int j = 0; j < 4; j++) v[j] = xr[j];

    float am = 0.0f;
    #pragma unroll
    for (int j = 0; j < 4; j++) {
        am = fmaxf(am, fmaxf(fmaxf(fabsf(v[j].x), fabsf(v[j].y)),
                             fmaxf(fabsf(v[j].z), fabsf(v[j].w))));
    }
    #pragma unroll
    for (int o = 16; o > 0; o >>= 1)
        am = fmaxf(am, __shfl_xor_sync(0xFFFFFFFFu, am, o));

    __shared__ float red[8];
    __shared__ float s_inv;
    if ((t & 31) == 0) red[t >> 5] = am;
    __syncthreads();
    if (t == 0) {
        float a = red[0];
        #pragma unroll
        for (int i = 1; i < 8; i++) a = fmaxf(a, red[i]);
        s_inv = (a > 0.0f) ? (16256.0f / a) : 0.0f;
        g_sx[m] = a * (1.0f / 16256.0f);
    }
    __syncthreads();
    const float inv = s_inv;

    int hp[4], lp[4];
    #pragma unroll
    for (int j = 0; j < 4; j++) {
        float q0 = rintf(v[j].x * inv), q1 = rintf(v[j].y * inv);
        float q2 = rintf(v[j].z * inv), q3 = rintf(v[j].w * inv);
        float h0 = rintf(q0 * 0.0078125f), h1 = rintf(q1 * 0.0078125f);
        float h2 = rintf(q2 * 0.0078125f), h3 = rintf(q3 * 0.0078125f);
        int l0 = (int)(q0 - 128.0f * h0), l1 = (int)(q1 - 128.0f * h1);
        int l2 = (int)(q2 - 128.0f * h2), l3 = (int)(q3 - 128.0f * h3);
        hp[j] = pack4((int)h0, (int)h1, (int)h2, (int)h3);
        lp[j] = pack4(l0, l1, l2, l3);
    }
    int4 hv = make_int4(hp[0], hp[1], hp[2], hp[3]);
    int4 lv = make_int4(lp[0], lp[1], lp[2], lp[3]);
    *reinterpret_cast<int4*>(g_Ahi + (size_t)m * KD + t * 16) = hv;
    *reinterpret_cast<int4*>(g_Alo + (size_t)m * KD + t * 16) = lv;
}

// ---------------------------------------------------------------------------
// Prep 2: d[n][k] = q[k][n] - zp[g(k)][n] as int8, transposed to [N,K].
// 32x32 tiles via SMEM. Block (32,8), grid (N/32, K/32).
// ---------------------------------------------------------------------------
__global__ __launch_bounds__(256) void diffT_kernel(
    const int* __restrict__ qw, const int* __restrict__ zp,
    const int* __restrict__ gidx) {
    __shared__ int8_t tile[32][33];
    const int tx = threadIdx.x;        // 0..31
    const int ty = threadIdx.y;        // 0..7
    const int n0 = blockIdx.x * 32;
    const int k0 = blockIdx.y * 32;

    #pragma unroll
    for (int i = 0; i < 4; i++) {
        int k = k0 + ty + 8 * i;
        int g = gidx[k];
        int q = qw[(size_t)k * ND + n0 + tx];
        int z = zp[(size_t)g * ND + n0 + tx];
        tile[ty + 8 * i][tx] = (int8_t)(q - z);
    }
    __syncthreads();

    const int id = ty * 32 + tx;       // 0..255
    const int r = id >> 3;             // n-row 0..31
    const int c = id & 7;              // k-quad 0..7
    int w = pack4(tile[4 * c][r], tile[4 * c + 1][r],
                  tile[4 * c + 2][r], tile[4 * c + 3][r]);
    *reinterpret_cast<int*>(g_Bd + (size_t)(n0 + r) * KD + k0 + 4 * c) = w;
}

// ---------------------------------------------------------------------------
// GEMM: C = sx_m * sum_g sc[g,n] * (128*S_hi + S_lo) + bias
// ---------------------------------------------------------------------------
__device__ __forceinline__ void load_stage(uint32_t sbase, int grp,
                                           int m0, int n0, int t) {
    const int k0 = grp * GK;
    #pragma unroll
    for (int u = 0; u < 4; u++) {
        int idx = t + u * THREADS;     // 0..1023
        int row = idx >> 3, seg = idx & 7;
        uint32_t so = row * ROWB + seg * 16;
        size_t ga = (size_t)(m0 + row) * KD + k0 + seg * 16;
        size_t gb = (size_t)(n0 + row) * KD + k0 + seg * 16;
        cp_async16(sbase + OFF_AH + so, g_Ahi + ga);
        cp_async16(sbase + OFF_AL + so, g_Alo + ga);
        cp_async16(sbase + OFF_B  + so, g_Bd  + gb);
    }
}

__global__ __launch_bounds__(THREADS, 1) void gemm_kernel(
    const float* __restrict__ scales,   // [NGROUPS, ND]
    const float* __restrict__ bias, float* __restrict__ C) {
    extern __shared__ char smem[];
    const uint32_t sb = smem_u32(smem);
    float* scs = reinterpret_cast<float*>(smem);        // [NGROUPS][BN]
    const uint32_t st0 = sb + SC_BYTES;

    const int t = threadIdx.x;
    const int lane = t & 31;
    const int wid = t >> 5;
    const int wm = wid >> 2;           // 0..1 : 64-row slice
    const int wn = wid & 3;            // 0..3 : 32-col slice
    const int m0 = blockIdx.y * BM;
    const int n0 = blockIdx.x * BN;

    // Preload 32x128 scale slab
    #pragma unroll
    for (int u = 0; u < 4; u++) {
        int i = t + u * THREADS;
        int g = i >> 5, j = i & 31;
        reinterpret_cast<float4*>(scs)[g * 32 + j] =
            *(reinterpret_cast<const float4*>(scales + (size_t)g * ND + n0) + j);
    }

    // ldmatrix per-thread base offsets (a0..a3 / b0,b1 fragment maps)
    const uint32_t a_base = (uint32_t)(wm * 64 + (lane & 15)) * ROWB + (lane >> 4) * 16;
    const uint32_t b_base = (uint32_t)(wn * 32 + (lane & 7) + ((lane >> 4) & 1) * 8) * ROWB
                          + ((lane >> 3) & 1) * 16;

    int   acc[4][4][4];
    float master[4][4][4];
    #pragma unroll
    for (int f = 0; f < 4; f++)
        #pragma unroll
        for (int n = 0; n < 4; n++)
            #pragma unroll
            for (int e = 0; e < 4; e++) { acc[f][n][e] = 0; master[f][n][e] = 0.0f; }

    load_stage(st0 + 0 * STAGE_BYTES, 0, m0, n0, t);
    cp_commit();
    load_stage(st0 + 1 * STAGE_BYTES, 1, m0, n0, t);
    cp_commit();

    const int col0 = (lane & 3) * 2;

    #pragma unroll 1
    for (int c = 0; c < NITER; c++) {
        asm volatile("cp.async.wait_group 1;" ::: "memory");
        __syncthreads();

        // prefetch (dup-last keeps wait_group accounting exact)
        {
            int pc = (c + 2 < NITER) ? (c + 2) : (NITER - 1);
            int ns = c + 2; ns -= (ns / STAGES) * STAGES;
            load_stage(st0 + ns * STAGE_BYTES, pc, m0, n0, t);
            cp_commit();
        }

        int sl = c; sl -= (sl / STAGES) * STAGES;
        const uint32_t stage = st0 + sl * STAGE_BYTES;

        // hi-digit phase: acc = S_hi
        #pragma unroll
        for (int s = 0; s < 4; s++) {
            uint32_t Af[4][4], Bf[2][4];
            #pragma unroll
            for (int f = 0; f < 4; f++)
                ldsm4(Af[f], stage + OFF_AH + a_base + f * (16 * ROWB) + s * 32);
            #pragma unroll
            for (int p = 0; p < 2; p++)
                ldsm4(Bf[p], stage + OFF_B + b_base + p * (16 * ROWB) + s * 32);
            #pragma unroll
            for (int f = 0; f < 4; f++)
                #pragma unroll
                for (int n = 0; n < 4; n++)
                    mma_s8(acc[f][n], Af[f], &Bf[n >> 1][(n & 1) * 2]);
        }

        // acc = 128*S_hi (exact int)
        #pragma unroll
        for (int f = 0; f < 4; f++)
            #pragma unroll
            for (int n = 0; n < 4; n++)
                #pragma unroll
                for (int e = 0; e < 4; e++) acc[f][n][e] <<= 7;

        // lo-digit phase: acc = 128*S_hi + S_lo
        #pragma unroll
        for (int s = 0; s < 4; s++) {
            uint32_t Af[4][4], Bf[2][4];
            #pragma unroll
            for (int f = 0; f < 4; f++)
                ldsm4(Af[f], stage + OFF_AL + a_base + f * (16 * ROWB) + s * 32);
            #pragma unroll
            for (int p = 0; p < 2; p++)
                ldsm4(Bf[p], stage + OFF_B + b_base + p * (16 * ROWB) + s * 32);
            #pragma unroll
            for (int f = 0; f < 4; f++)
                #pragma unroll
                for (int n = 0; n < 4; n++)
                    mma_s8(acc[f][n], Af[f], &Bf[n >> 1][(n & 1) * 2]);
        }

        // fold group scale
        #pragma unroll
        for (int n = 0; n < 4; n++) {
            const float2 s2 = *reinterpret_cast<const float2*>(
                scs + c * BN + wn * 32 + n * 8 + col0);
            #pragma unroll
            for (int f = 0; f < 4; f++) {
                master[f][n][0] += s2.x * (float)acc[f][n][0];
                master[f][n][1] += s2.y * (float)acc[f][n][1];
                master[f][n][2] += s2.x * (float)acc[f][n][2];
                master[f][n][3] += s2.y * (float)acc[f][n][3];
                acc[f][n][0] = 0; acc[f][n][1] = 0;
                acc[f][n][2] = 0; acc[f][n][3] = 0;
            }
        }
    }

    // Epilogue: out = sx_m * master + bias
    const int row0 = lane >> 2;
    #pragma unroll
    for (int f = 0; f < 4; f++) {
        const int gr = m0 + wm * 64 + f * 16 + row0;
        const float sx0 = g_sx[gr];
        const float sx1 = g_sx[gr + 8];
        #pragma unroll
        for (int n = 0; n < 4; n++) {
            const int gc = n0 + wn * 32 + n * 8 + col0;
            const float2 bb = *reinterpret_cast<const float2*>(bias + gc);
            float2 o0, o1;
            o0.x = sx0 * master[f][n][0] + bb.x;
            o0.y = sx0 * master[f][n][1] + bb.y;
            o1.x = sx1 * master[f][n][2] + bb.x;
            o1.y = sx1 * master[f][n][3] + bb.y;
            *reinterpret_cast<float2*>(C + (size_t)gr * ND + gc) = o0;
            *reinterpret_cast<float2*>(C + (size_t)(gr + 8) * ND + gc) = o1;
        }
    }
}

// ---------------------------------------------------------------------------
// Launch. Inputs: x, qweight_int, scales, zero_points, g_idx, bias. Out: fp32.
// ---------------------------------------------------------------------------
extern "C" void kernel_launch(void* const* d_in, const int* in_sizes, int n_in,
                              void* d_out, int out_size) {
    const float* x    = (const float*)d_in[0];
    const int*   qw   = (const int*)  d_in[1];
    const float* sc   = (const float*)d_in[2];
    const int*   zp   = (const int*)  d_in[3];
    const int*   gidx = (const int*)  d_in[4];
    const float* bias = (const float*)d_in[5];
    float*       out  = (float*)d_out;

    const int M = in_sizes[0] / KD;   // 4096

    cudaFuncSetAttribute(gemm_kernel,
                         cudaFuncAttributeMaxDynamicSharedMemorySize, SMEM_TOTAL);

    quant_x_kernel<<<M, 256>>>(x);
    diffT_kernel<<<dim3(ND / 32, KD / 32), dim3(32, 8)>>>(qw, zp, gidx);
    gemm_kernel<<<dim3(ND / BN, M / BM), THREADS, SMEM_TOTAL>>>(sc, bias, out);
}

// round 11
// speedup vs baseline: 2.1878x; 2.1878x over previous
#include <cuda_runtime.h>
#include <cuda_bf16.h>
#include <cstdint>

// ---------------------------------------------------------------------------
// Problem constants
// ---------------------------------------------------------------------------
static constexpr int KD = 4096;
static constexpr int ND = 4096;
static constexpr int MD = 4096;
static constexpr int NGROUPS = 32;       // K groups of 128

// GEMM tiling
static constexpr int BM = 128;
static constexpr int BN = 128;
static constexpr int BK = 32;
static constexpr int STAGES = 4;
static constexpr int NCHUNK = KD / BK;   // 128 ; scale group = 4 chunks
static constexpr int THREADS = 512;      // 16 warps -> 4 warps/SMSP

// SMEM stage layout (padded rows -> conflict-reduced ldmatrix phases)
static constexpr int A_ROWB = 80;              // 64B data + 16B pad
static constexpr int B_ROWB = 272;             // 256B data + 16B pad
static constexpr int SZ_A = BM * A_ROWB;       // 10240
static constexpr int SZ_B = BK * B_ROWB;       // 8704
static constexpr int OFF_AH = 0;
static constexpr int OFF_AL = SZ_A;
static constexpr int OFF_BD = 2 * SZ_A;
static constexpr int STAGE_BYTES = 2 * SZ_A + SZ_B;            // 29184
static constexpr int SC_BYTES = NGROUPS * BN * 4;              // 16384
static constexpr int SMEM_TOTAL = SC_BYTES + STAGES * STAGE_BYTES;  // 133120

// ---------------------------------------------------------------------------
// Scratch: A (x) split bf16 hi/lo [M,K]; B = (q - zp) exact ints as bf16 [K,N]
// ---------------------------------------------------------------------------
__device__ __nv_bfloat16 g_Ah[(size_t)MD * KD];
__device__ __nv_bfloat16 g_Al[(size_t)MD * KD];
__device__ __nv_bfloat16 g_Bd[(size_t)KD * ND];

// ---------------------------------------------------------------------------
// PTX helpers
// ---------------------------------------------------------------------------
__device__ __forceinline__ uint32_t smem_u32(const void* p) {
    uint32_t a;
    asm("{ .reg .u64 t; cvta.to.shared.u64 t, %1; cvt.u32.u64 %0, t; }" : "=r"(a) : "l"(p));
    return a;
}
__device__ __forceinline__ void cp_async16(uint32_t dst, const void* src) {
    asm volatile("cp.async.cg.shared.global [%0], [%1], 16;" :: "r"(dst), "l"(src));
}
__device__ __forceinline__ void cp_commit() {
    asm volatile("cp.async.commit_group;" ::: "memory");
}
__device__ __forceinline__ void ldsm4(uint32_t* r, uint32_t addr) {
    asm volatile("ldmatrix.sync.aligned.m8n8.x4.shared.b16 {%0,%1,%2,%3}, [%4];"
                 : "=r"(r[0]), "=r"(r[1]), "=r"(r[2]), "=r"(r[3]) : "r"(addr));
}
__device__ __forceinline__ void ldsm4t(uint32_t* r, uint32_t addr) {
    asm volatile("ldmatrix.sync.aligned.m8n8.x4.trans.shared.b16 {%0,%1,%2,%3}, [%4];"
                 : "=r"(r[0]), "=r"(r[1]), "=r"(r[2]), "=r"(r[3]) : "r"(addr));
}
__device__ __forceinline__ void mma_bf16(float* c, const uint32_t* a, const uint32_t* b) {
    asm volatile(
        "mma.sync.aligned.m16n8k16.row.col.f32.bf16.bf16.f32 "
        "{%0,%1,%2,%3}, {%4,%5,%6,%7}, {%8,%9}, {%0,%1,%2,%3};"
        : "+f"(c[0]), "+f"(c[1]), "+f"(c[2]), "+f"(c[3])
        : "r"(a[0]), "r"(a[1]), "r"(a[2]), "r"(a[3]), "r"(b[0]), "r"(b[1]));
}

// ---------------------------------------------------------------------------
// Prep 1: split x (fp32 [M,K]) into bf16 hi/lo
// ---------------------------------------------------------------------------
__global__ __launch_bounds__(256) void split_x_kernel(const float* __restrict__ x) {
    size_t i = (size_t)blockIdx.x * 256 + threadIdx.x;   // over M*K/4
    float4 v = reinterpret_cast<const float4*>(x)[i];

    __nv_bfloat16 h0 = __float2bfloat16(v.x), h1 = __float2bfloat16(v.y);
    __nv_bfloat16 h2 = __float2bfloat16(v.z), h3 = __float2bfloat16(v.w);
    __nv_bfloat16 l0 = __float2bfloat16(v.x - __bfloat162float(h0));
    __nv_bfloat16 l1 = __float2bfloat16(v.y - __bfloat162float(h1));
    __nv_bfloat16 l2 = __float2bfloat16(v.z - __bfloat162float(h2));
    __nv_bfloat16 l3 = __float2bfloat16(v.w - __bfloat162float(h3));

    reinterpret_cast<__nv_bfloat162*>(g_Ah)[i * 2 + 0] = __nv_bfloat162(h0, h1);
    reinterpret_cast<__nv_bfloat162*>(g_Ah)[i * 2 + 1] = __nv_bfloat162(h2, h3);
    reinterpret_cast<__nv_bfloat162*>(g_Al)[i * 2 + 0] = __nv_bfloat162(l0, l1);
    reinterpret_cast<__nv_bfloat162*>(g_Al)[i * 2 + 1] = __nv_bfloat162(l2, l3);
}

// ---------------------------------------------------------------------------
// Prep 2: d[k][n] = q[k][n] - zp[g(k)][n]  (small int, EXACT in bf16)
// ---------------------------------------------------------------------------
__global__ __launch_bounds__(256) void diff_kernel(
    const int* __restrict__ qw, const int* __restrict__ zp,
    const int* __restrict__ gidx) {
    size_t idx = (size_t)blockIdx.x * 256 + threadIdx.x;   // over K*N/4
    int n4 = (int)(idx & (ND / 4 - 1));
    int k  = (int)(idx >> 10);
    int g  = gidx[k];

    int4 q = reinterpret_cast<const int4*>(qw + (size_t)k * ND)[n4];
    int4 z = reinterpret_cast<const int4*>(zp + (size_t)g * ND)[n4];

    __nv_bfloat16 d0 = __float2bfloat16((float)(q.x - z.x));
    __nv_bfloat16 d1 = __float2bfloat16((float)(q.y - z.y));
    __nv_bfloat16 d2 = __float2bfloat16((float)(q.z - z.z));
    __nv_bfloat16 d3 = __float2bfloat16((float)(q.w - z.w));

    reinterpret_cast<__nv_bfloat162*>(g_Bd)[idx * 2 + 0] = __nv_bfloat162(d0, d1);
    reinterpret_cast<__nv_bfloat162*>(g_Bd)[idx * 2 + 1] = __nv_bfloat162(d2, d3);
}

// ---------------------------------------------------------------------------
// GEMM: C = x @ (sc * d) + bias ; scales factored out per K-group.
// 512 threads, 16 warps (4x4), warp tile 32x32.
// ---------------------------------------------------------------------------
__device__ __forceinline__ void load_stage(uint32_t sbase, int chunk,
                                           int m0, int n0, int t) {
    const int k0 = chunk * BK;
    // A tiles: 128 rows x 4 segs of 16B = 512 segments each (hi and lo)
    {
        int row = t >> 2, seg = t & 3;
        uint32_t so = row * A_ROWB + seg * 16;
        size_t go = (size_t)(m0 + row) * KD + k0 + seg * 8;
        cp_async16(sbase + OFF_AH + so, g_Ah + go);
        cp_async16(sbase + OFF_AL + so, g_Al + go);
    }
    // B tile: 32 rows x 16 segs of 16B = 512 segments
    {
        int row = t >> 4, seg = t & 15;
        uint32_t so = row * B_ROWB + seg * 16;
        size_t go = (size_t)(k0 + row) * ND + n0 + seg * 8;
        cp_async16(sbase + OFF_BD + so, g_Bd + go);
    }
}

__global__ __launch_bounds__(THREADS, 1) void gemm_kernel(
    const float* __restrict__ scales,   // [NGROUPS, ND]
    const float* __restrict__ bias, float* __restrict__ C) {
    extern __shared__ char smem[];
    const uint32_t sb = smem_u32(smem);
    float* scs = reinterpret_cast<float*>(smem);          // [NGROUPS][BN]
    const uint32_t stage0 = sb + SC_BYTES;

    const int t = threadIdx.x;
    const int lane = t & 31;
    const int wid = t >> 5;            // 0..15
    const int wm = wid >> 2;           // 0..3  (32-row slice)
    const int wn = wid & 3;            // 0..3  (32-col slice)
    const int m0 = blockIdx.y * BM;
    const int n0 = blockIdx.x * BN;

    // Preload the 32x128 scale slab for this CTA's columns.
    #pragma unroll
    for (int u = 0; u < 2; u++) {
        int i = t + u * THREADS;           // 0..1023 float4s
        int g = i >> 5, j4 = i & 31;
        reinterpret_cast<float4*>(scs)[(size_t)g * 32 + j4] =
            *reinterpret_cast<const float4*>(scales + (size_t)g * ND + n0 + j4 * 4);
    }

    // ldmatrix per-thread base offsets
    const uint32_t a_off0 = (uint32_t)(wm * 32 + (lane & 15)) * A_ROWB + (lane >> 4) * 16;
    const uint32_t b_off0 = (uint32_t)(lane & 15) * B_ROWB + wn * 64 + (lane >> 4) * 16;

    float master[2][4][4];
    float part[2][4][4];
    #pragma unroll
    for (int f = 0; f < 2; f++)
        #pragma unroll
        for (int n = 0; n < 4; n++)
            #pragma unroll
            for (int e = 0; e < 4; e++) {
                master[f][n][e] = 0.0f;
                part[f][n][e] = 0.0f;
            }

    // Prologue: stages 0..2
    load_stage(stage0 + 0 * STAGE_BYTES, 0, m0, n0, t);
    cp_commit();
    load_stage(stage0 + 1 * STAGE_BYTES, 1, m0, n0, t);
    cp_commit();
    load_stage(stage0 + 2 * STAGE_BYTES, 2, m0, n0, t);
    cp_commit();

    const int col0 = (lane & 3) * 2;

    #pragma unroll 1
    for (int c = 0; c < NCHUNK; c++) {
        const int slot = c & 3;
        asm volatile("cp.async.wait_group 2;" ::: "memory");
        __syncthreads();

        // Prefetch one REAL group every iteration (dup reload of last chunk in
        // the tail keeps wait_group depth accounting exact).
        {
            int pc = (c + 3 < NCHUNK) ? (c + 3) : (NCHUNK - 1);
            load_stage(stage0 + ((c + 3) & 3) * STAGE_BYTES, pc, m0, n0, t);
            cp_commit();
        }

        const uint32_t stage = stage0 + slot * STAGE_BYTES;

        #pragma unroll
        for (int ks = 0; ks < 2; ks++) {
            uint32_t Ah[2][4], Al[2][4], Bd[4][2];
            #pragma unroll
            for (int f = 0; f < 2; f++) {
                uint32_t ao = a_off0 + f * 16 * A_ROWB + ks * 32;
                ldsm4(Ah[f], stage + OFF_AH + ao);
                ldsm4(Al[f], stage + OFF_AL + ao);
            }
            #pragma unroll
            for (int p = 0; p < 2; p++) {
                uint32_t bo = b_off0 + ks * 16 * B_ROWB + p * 32;
                uint32_t tmp[4];
                ldsm4t(tmp, stage + OFF_BD + bo);
                Bd[2 * p][0] = tmp[0]; Bd[2 * p][1] = tmp[1];
                Bd[2 * p + 1][0] = tmp[2]; Bd[2 * p + 1][1] = tmp[3];
            }
            #pragma unroll
            for (int f = 0; f < 2; f++)
                #pragma unroll
                for (int n = 0; n < 4; n++)
                    mma_bf16(part[f][n], Ah[f], Bd[n]);
            #pragma unroll
            for (int f = 0; f < 2; f++)
                #pragma unroll
                for (int n = 0; n < 4; n++)
                    mma_bf16(part[f][n], Al[f], Bd[n]);
        }

        // End of a K-group (4 chunks): fold scaled partials into master.
        if ((c & 3) == 3) {
            const int g = c >> 2;
            #pragma unroll
            for (int n = 0; n < 4; n++) {
                const float2 s2 = *reinterpret_cast<const float2*>(
                    scs + (size_t)g * BN + wn * 32 + n * 8 + col0);
                #pragma unroll
                for (int f = 0; f < 2; f++) {
                    master[f][n][0] += s2.x * part[f][n][0];
                    master[f][n][1] += s2.y * part[f][n][1];
                    master[f][n][2] += s2.x * part[f][n][2];
                    master[f][n][3] += s2.y * part[f][n][3];
                    part[f][n][0] = 0.0f; part[f][n][1] = 0.0f;
                    part[f][n][2] = 0.0f; part[f][n][3] = 0.0f;
                }
            }
        }
    }

    // Epilogue: bias + store
    const int row0 = lane >> 2;
    #pragma unroll
    for (int n = 0; n < 4; n++) {
        const int gc = n0 + wn * 32 + n * 8 + col0;
        const float2 bb = *reinterpret_cast<const float2*>(bias + gc);
        #pragma unroll
        for (int f = 0; f < 2; f++) {
            const int gr = m0 + wm * 32 + f * 16 + row0;
            float2 o0, o1;
            o0.x = master[f][n][0] + bb.x;
            o0.y = master[f][n][1] + bb.y;
            o1.x = master[f][n][2] + bb.x;
            o1.y = master[f][n][3] + bb.y;
            *reinterpret_cast<float2*>(C + (size_t)gr * ND + gc) = o0;
            *reinterpret_cast<float2*>(C + (size_t)(gr + 8) * ND + gc) = o1;
        }
    }
}

// ---------------------------------------------------------------------------
// Launch. Inputs: x, qweight_int, scales, zero_points, g_idx, bias. Out: fp32.
// ---------------------------------------------------------------------------
extern "C" void kernel_launch(void* const* d_in, const int* in_sizes, int n_in,
                              void* d_out, int out_size) {
    const float* x    = (const float*)d_in[0];
    const int*   qw   = (const int*)  d_in[1];
    const float* sc   = (const float*)d_in[2];
    const int*   zp   = (const int*)  d_in[3];
    const int*   gidx = (const int*)  d_in[4];
    const float* bias = (const float*)d_in[5];
    float*       out  = (float*)d_out;

    const int M = in_sizes[0] / KD;   // 4096

    cudaFuncSetAttribute(gemm_kernel,
                         cudaFuncAttributeMaxDynamicSharedMemorySize, SMEM_TOTAL);

    split_x_kernel<<<(M * KD / 4) / 256, 256>>>(x);
    diff_kernel<<<(KD * (ND / 4)) / 256, 256>>>(qw, zp, gidx);
    gemm_kernel<<<dim3(ND / BN, M / BM), THREADS, SMEM_TOTAL>>>(sc, bias, out);
}

// round 14
// speedup vs baseline: 3.6179x; 1.6537x over previous
#include <cuda_runtime.h>
#include <cuda_fp16.h>
#include <cstdint>

// ---------------------------------------------------------------------------
// Problem constants
// ---------------------------------------------------------------------------
static constexpr int KD = 4096;
static constexpr int ND = 4096;
static constexpr int MD = 4096;
static constexpr int NGROUPS = 32;       // K groups of 128

// GEMM tiling
static constexpr int BM = 128;
static constexpr int BN = 128;
static constexpr int BK = 32;
static constexpr int STAGES = 4;
static constexpr int NCHUNK = KD / BK;   // 128 ; scale group = 4 chunks
static constexpr int THREADS = 512;      // 16 warps

// SMEM stage layout (padded rows -> conflict-reduced ldmatrix phases)
static constexpr int A_ROWB = 80;              // 64B data + 16B pad
static constexpr int B_ROWB = 272;             // 256B data + 16B pad
static constexpr int SZ_A = BM * A_ROWB;       // 10240
static constexpr int SZ_B = BK * B_ROWB;       // 8704
static constexpr int OFF_A = 0;
static constexpr int OFF_B = SZ_A;
static constexpr int STAGE_BYTES = SZ_A + SZ_B;                // 18944
static constexpr int SC_BYTES = NGROUPS * BN * 4;              // 16384
static constexpr int SMEM_TOTAL = SC_BYTES + STAGES * STAGE_BYTES;  // 92160

// ---------------------------------------------------------------------------
// Scratch: A (x) fp16 [M,K]; B = (q - zp) exact small ints as fp16 [K,N]
// ---------------------------------------------------------------------------
__device__ __half g_Ax[(size_t)MD * KD];
__device__ __half g_Bd[(size_t)KD * ND];

// ---------------------------------------------------------------------------
// PTX helpers
// ---------------------------------------------------------------------------
__device__ __forceinline__ uint32_t smem_u32(const void* p) {
    uint32_t a;
    asm("{ .reg .u64 t; cvta.to.shared.u64 t, %1; cvt.u32.u64 %0, t; }" : "=r"(a) : "l"(p));
    return a;
}
__device__ __forceinline__ void cp_async16(uint32_t dst, const void* src) {
    asm volatile("cp.async.cg.shared.global [%0], [%1], 16;" :: "r"(dst), "l"(src));
}
__device__ __forceinline__ void cp_commit() {
    asm volatile("cp.async.commit_group;" ::: "memory");
}
__device__ __forceinline__ void ldsm4(uint32_t* r, uint32_t addr) {
    asm volatile("ldmatrix.sync.aligned.m8n8.x4.shared.b16 {%0,%1,%2,%3}, [%4];"
                 : "=r"(r[0]), "=r"(r[1]), "=r"(r[2]), "=r"(r[3]) : "r"(addr));
}
__device__ __forceinline__ void ldsm4t(uint32_t* r, uint32_t addr) {
    asm volatile("ldmatrix.sync.aligned.m8n8.x4.trans.shared.b16 {%0,%1,%2,%3}, [%4];"
                 : "=r"(r[0]), "=r"(r[1]), "=r"(r[2]), "=r"(r[3]) : "r"(addr));
}
__device__ __forceinline__ void mma_f16(float* c, const uint32_t* a, const uint32_t* b) {
    asm volatile(
        "mma.sync.aligned.m16n8k16.row.col.f32.f16.f16.f32 "
        "{%0,%1,%2,%3}, {%4,%5,%6,%7}, {%8,%9}, {%0,%1,%2,%3};"
        : "+f"(c[0]), "+f"(c[1]), "+f"(c[2]), "+f"(c[3])
        : "r"(a[0]), "r"(a[1]), "r"(a[2]), "r"(a[3]), "r"(b[0]), "r"(b[1]));
}

// ---------------------------------------------------------------------------
// Prep 1: convert x (fp32 [M,K]) to fp16
// ---------------------------------------------------------------------------
__global__ __launch_bounds__(256) void conv_x_kernel(const float* __restrict__ x) {
    size_t i = (size_t)blockIdx.x * 256 + threadIdx.x;   // over M*K/4
    float4 v = reinterpret_cast<const float4*>(x)[i];
    __half2 p0 = __floats2half2_rn(v.x, v.y);
    __half2 p1 = __floats2half2_rn(v.z, v.w);
    reinterpret_cast<__half2*>(g_Ax)[i * 2 + 0] = p0;
    reinterpret_cast<__half2*>(g_Ax)[i * 2 + 1] = p1;
}

// ---------------------------------------------------------------------------
// Prep 2: d[k][n] = q[k][n] - zp[g(k)][n]  (small int, EXACT in fp16)
// ---------------------------------------------------------------------------
__global__ __launch_bounds__(256) void diff_kernel(
    const int* __restrict__ qw, const int* __restrict__ zp,
    const int* __restrict__ gidx) {
    size_t idx = (size_t)blockIdx.x * 256 + threadIdx.x;   // over K*N/4
    int n4 = (int)(idx & (ND / 4 - 1));
    int k  = (int)(idx >> 10);
    int g  = gidx[k];

    int4 q = reinterpret_cast<const int4*>(qw + (size_t)k * ND)[n4];
    int4 z = reinterpret_cast<const int4*>(zp + (size_t)g * ND)[n4];

    __half2 d0 = __floats2half2_rn((float)(q.x - z.x), (float)(q.y - z.y));
    __half2 d1 = __floats2half2_rn((float)(q.z - z.z), (float)(q.w - z.w));
    reinterpret_cast<__half2*>(g_Bd)[idx * 2 + 0] = d0;
    reinterpret_cast<__half2*>(g_Bd)[idx * 2 + 1] = d1;
}

// ---------------------------------------------------------------------------
// GEMM: C = x @ (sc * d) + bias ; scales factored out per K-group.
// 512 threads, 16 warps (4x4), warp tile 32x32, single fp16 term.
// ---------------------------------------------------------------------------
__device__ __forceinline__ void load_stage(uint32_t sbase, int chunk,
                                           int m0, int n0, int t) {
    const int k0 = chunk * BK;
    // A tile: 128 rows x 4 segs of 16B = 512 segments
    {
        int row = t >> 2, seg = t & 3;
        uint32_t so = row * A_ROWB + seg * 16;
        size_t go = (size_t)(m0 + row) * KD + k0 + seg * 8;
        cp_async16(sbase + OFF_A + so, g_Ax + go);
    }
    // B tile: 32 rows x 16 segs of 16B = 512 segments
    {
        int row = t >> 4, seg = t & 15;
        uint32_t so = row * B_ROWB + seg * 16;
        size_t go = (size_t)(k0 + row) * ND + n0 + seg * 8;
        cp_async16(sbase + OFF_B + so, g_Bd + go);
    }
}

__global__ __launch_bounds__(THREADS, 1) void gemm_kernel(
    const float* __restrict__ scales,   // [NGROUPS, ND]
    const float* __restrict__ bias, float* __restrict__ C) {
    extern __shared__ char smem[];
    const uint32_t sb = smem_u32(smem);
    float* scs = reinterpret_cast<float*>(smem);          // [NGROUPS][BN]
    const uint32_t stage0 = sb + SC_BYTES;

    const int t = threadIdx.x;
    const int lane = t & 31;
    const int wid = t >> 5;            // 0..15
    const int wm = wid >> 2;           // 0..3  (32-row slice)
    const int wn = wid & 3;            // 0..3  (32-col slice)
    const int m0 = blockIdx.y * BM;
    const int n0 = blockIdx.x * BN;

    // Preload the 32x128 scale slab for this CTA's columns.
    #pragma unroll
    for (int u = 0; u < 2; u++) {
        int i = t + u * THREADS;           // 0..1023 float4s
        int g = i >> 5, j4 = i & 31;
        reinterpret_cast<float4*>(scs)[(size_t)g * 32 + j4] =
            *reinterpret_cast<const float4*>(scales + (size_t)g * ND + n0 + j4 * 4);
    }

    // ldmatrix per-thread base offsets
    const uint32_t a_off0 = (uint32_t)(wm * 32 + (lane & 15)) * A_ROWB + (lane >> 4) * 16;
    const uint32_t b_off0 = (uint32_t)(lane & 15) * B_ROWB + wn * 64 + (lane >> 4) * 16;

    float master[2][4][4];
    float part[2][4][4];
    #pragma unroll
    for (int f = 0; f < 2; f++)
        #pragma unroll
        for (int n = 0; n < 4; n++)
            #pragma unroll
            for (int e = 0; e < 4; e++) {
                master[f][n][e] = 0.0f;
                part[f][n][e] = 0.0f;
            }

    // Prologue: stages 0..2
    load_stage(stage0 + 0 * STAGE_BYTES, 0, m0, n0, t);
    cp_commit();
    load_stage(stage0 + 1 * STAGE_BYTES, 1, m0, n0, t);
    cp_commit();
    load_stage(stage0 + 2 * STAGE_BYTES, 2, m0, n0, t);
    cp_commit();

    const int col0 = (lane & 3) * 2;

    #pragma unroll 1
    for (int c = 0; c < NCHUNK; c++) {
        const int slot = c & 3;
        asm volatile("cp.async.wait_group 2;" ::: "memory");
        __syncthreads();

        // Prefetch one REAL group every iteration (dup reload of last chunk in
        // the tail keeps wait_group depth accounting exact).
        {
            int pc = (c + 3 < NCHUNK) ? (c + 3) : (NCHUNK - 1);
            load_stage(stage0 + ((c + 3) & 3) * STAGE_BYTES, pc, m0, n0, t);
            cp_commit();
        }

        const uint32_t stage = stage0 + slot * STAGE_BYTES;

        #pragma unroll
        for (int ks = 0; ks < 2; ks++) {
            uint32_t Af[2][4], Bd[4][2];
            #pragma unroll
            for (int f = 0; f < 2; f++) {
                uint32_t ao = a_off0 + f * 16 * A_ROWB + ks * 32;
                ldsm4(Af[f], stage + OFF_A + ao);
            }
            #pragma unroll
            for (int p = 0; p < 2; p++) {
                uint32_t bo = b_off0 + ks * 16 * B_ROWB + p * 32;
                uint32_t tmp[4];
                ldsm4t(tmp, stage + OFF_B + bo);
                Bd[2 * p][0] = tmp[0]; Bd[2 * p][1] = tmp[1];
                Bd[2 * p + 1][0] = tmp[2]; Bd[2 * p + 1][1] = tmp[3];
            }
            #pragma unroll
            for (int f = 0; f < 2; f++)
                #pragma unroll
                for (int n = 0; n < 4; n++)
                    mma_f16(part[f][n], Af[f], Bd[n]);
        }

        // End of a K-group (4 chunks): fold scaled partials into master.
        if ((c & 3) == 3) {
            const int g = c >> 2;
            #pragma unroll
            for (int n = 0; n < 4; n++) {
                const float2 s2 = *reinterpret_cast<const float2*>(
                    scs + (size_t)g * BN + wn * 32 + n * 8 + col0);
                #pragma unroll
                for (int f = 0; f < 2; f++) {
                    master[f][n][0] += s2.x * part[f][n][0];
                    master[f][n][1] += s2.y * part[f][n][1];
                    master[f][n][2] += s2.x * part[f][n][2];
                    master[f][n][3] += s2.y * part[f][n][3];
                    part[f][n][0] = 0.0f; part[f][n][1] = 0.0f;
                    part[f][n][2] = 0.0f; part[f][n][3] = 0.0f;
                }
            }
        }
    }

    // Epilogue: bias + store
    const int row0 = lane >> 2;
    #pragma unroll
    for (int n = 0; n < 4; n++) {
        const int gc = n0 + wn * 32 + n * 8 + col0;
        const float2 bb = *reinterpret_cast<const float2*>(bias + gc);
        #pragma unroll
        for (int f = 0; f < 2; f++) {
            const int gr = m0 + wm * 32 + f * 16 + row0;
            float2 o0, o1;
            o0.x = master[f][n][0] + bb.x;
            o0.y = master[f][n][1] + bb.y;
            o1.x = master[f][n][2] + bb.x;
            o1.y = master[f][n][3] + bb.y;
            *reinterpret_cast<float2*>(C + (size_t)gr * ND + gc) = o0;
            *reinterpret_cast<float2*>(C + (size_t)(gr + 8) * ND + gc) = o1;
        }
    }
}

// ---------------------------------------------------------------------------
// Launch. Inputs: x, qweight_int, scales, zero_points, g_idx, bias. Out: fp32.
// ---------------------------------------------------------------------------
extern "C" void kernel_launch(void* const* d_in, const int* in_sizes, int n_in,
                              void* d_out, int out_size) {
    const float* x    = (const float*)d_in[0];
    const int*   qw   = (const int*)  d_in[1];
    const float* sc   = (const float*)d_in[2];
    const int*   zp   = (const int*)  d_in[3];
    const int*   gidx = (const int*)  d_in[4];
    const float* bias = (const float*)d_in[5];
    float*       out  = (float*)d_out;

    const int M = in_sizes[0] / KD;   // 4096

    cudaFuncSetAttribute(gemm_kernel,
                         cudaFuncAttributeMaxDynamicSharedMemorySize, SMEM_TOTAL);

    conv_x_kernel<<<(M * KD / 4) / 256, 256>>>(x);
    diff_kernel<<<(KD * (ND / 4)) / 256, 256>>>(qw, zp, gidx);
    gemm_kernel<<<dim3(ND / BN, M / BM), THREADS, SMEM_TOTAL>>>(sc, bias, out);
}